// round 7
// baseline (speedup 1.0000x reference)
#include <cuda_runtime.h>
#include <cuda_fp16.h>
#include <cstdint>

#define BATCH 4
#define SEQ   4096
#define DIN   128
#define DOUT  64
#define BQ    128
#define BK    128
#define NTILES (SEQ / BK)

// Q pre-scale: 1/sqrt(64) * log2(e)  (softmax runs in exp2 domain)
#define QSCALE 0.1803368801111244f

// ---- fp16 scratch — device globals, no allocation ----
__device__ __half g_qh[BATCH * SEQ * DOUT];
__device__ __half g_ql[BATCH * SEQ * DOUT];
__device__ __half g_kh[BATCH * SEQ * DOUT];
__device__ __half g_kl[BATCH * SEQ * DOUT];
__device__ __half g_vt[BATCH * DOUT * SEQ];   // transposed: [b][dout][seq]

// ---- attn smem: 3-stage KV pipeline ----
#define QH_B      0
#define QL_B      18432
#define ST_B(s)   (36864 + (s) * 54272)
#define KH_B(s)   (ST_B(s))
#define KL_B(s)   (ST_B(s) + 18432)
#define VT_B(s)   (ST_B(s) + 36864)
#define SMEM_BYTES 199680

typedef unsigned long long u64;

__device__ __forceinline__ uint32_t smem_u32(const void* p) {
    uint32_t a;
    asm("{ .reg .u64 t; cvta.to.shared.u64 t, %1; cvt.u32.u64 %0, t; }" : "=r"(a) : "l"(p));
    return a;
}
__device__ __forceinline__ void cp16(uint32_t dst, const void* src) {
    asm volatile("cp.async.cg.shared.global [%0], [%1], 16;" :: "r"(dst), "l"(src));
}
#define CP_COMMIT() asm volatile("cp.async.commit_group;" ::: "memory")
#define CP_WAIT1()  asm volatile("cp.async.wait_group 1;" ::: "memory")

__device__ __forceinline__ float ex2f(float x) {
    float r; asm("ex2.approx.ftz.f32 %0, %1;" : "=f"(r) : "f"(x)); return r;
}

#define MMA16816(c, a0, a1, a2, a3, b0, b1) \
    asm volatile("mma.sync.aligned.m16n8k16.row.col.f32.f16.f16.f32 " \
                 "{%0,%1,%2,%3}, {%4,%5,%6,%7}, {%8,%9}, {%0,%1,%2,%3};" \
                 : "+f"((c)[0]), "+f"((c)[1]), "+f"((c)[2]), "+f"((c)[3]) \
                 : "r"(a0), "r"(a1), "r"(a2), "r"(a3), "r"(b0), "r"(b1))

#define LDMX4(r0, r1, r2, r3, a) \
    asm volatile("ldmatrix.sync.aligned.m8n8.x4.shared.b16 {%0,%1,%2,%3}, [%4];" \
                 : "=r"(r0), "=r"(r1), "=r"(r2), "=r"(r3) : "r"(a))

// ---- packed f32x2 ----
__device__ __forceinline__ u64 pk2(float lo, float hi) {
    u64 r; asm("mov.b64 %0, {%1, %2};" : "=l"(r) : "f"(lo), "f"(hi)); return r;
}
__device__ __forceinline__ void fma2(u64& d, u64 a, u64 b) {
    asm("fma.rn.f32x2 %0, %1, %2, %0;" : "+l"(d) : "l"(a), "l"(b));
}
__device__ __forceinline__ void upk2(u64 v, float& lo, float& hi) {
    asm("mov.b64 {%0, %1}, %2;" : "=f"(lo), "=f"(hi) : "l"(v));
}

// ---------------------------------------------------------------------------
// Kernel 1: QKV projection. x staged in smem as duplicated f32x2 pairs so
// LDS.64 feeds fma2 directly (no per-element packing MOVs).
// ---------------------------------------------------------------------------
#define XS2_PAD  132                     // u64 per x row (128 + 4 pad)
#define VTS_PAD  132                     // halves per vts row
#define QKV_XS_B 0                       // 128 * 132 * 8 = 135168
#define QKV_VT_B 135168                  // 64 * 132 * 2  = 16896
#define QKV_SMEM 152064

__global__ __launch_bounds__(256)
void qkv_proj_kernel(const float* __restrict__ x,
                     const float* __restrict__ w) {
    extern __shared__ __align__(16) char qsm[];
    u64*    xs2 = (u64*)(qsm + QKV_XS_B);       // [token][d] as (x,x)
    __half* vts = (__half*)(qsm + QKV_VT_B);    // [e][token]

    const int b   = blockIdx.y;
    const int n0  = blockIdx.x * 128;
    const int tid = threadIdx.x;

    const float* xg = x + ((size_t)(b * SEQ + n0)) * DIN;
#pragma unroll
    for (int i = 0; i < 16; i++) {
        const int id4 = tid + i * 256;
        const int tok = id4 >> 5, c4 = (id4 & 31) << 2;
        const float4 v = *(const float4*)&xg[tok * DIN + c4];
        u64* dst = &xs2[tok * XS2_PAD + c4];
        dst[0] = pk2(v.x, v.x); dst[1] = pk2(v.y, v.y);
        dst[2] = pk2(v.z, v.z); dst[3] = pk2(v.w, v.w);
    }
    __syncthreads();

    const int tx = tid & 31, ty = tid >> 5;
    const int tok0 = ty * 16;

    u64 acc[16][3];
#pragma unroll
    for (int t = 0; t < 16; t++)
#pragma unroll
        for (int p = 0; p < 3; p++) acc[t][p] = 0ull;

#pragma unroll 2
    for (int d = 0; d < DIN; d++) {
        const u64 wq = pk2(w[(0 * DIN + d) * DOUT + tx], w[(0 * DIN + d) * DOUT + tx + 32]);
        const u64 wk = pk2(w[(1 * DIN + d) * DOUT + tx], w[(1 * DIN + d) * DOUT + tx + 32]);
        const u64 wv = pk2(w[(2 * DIN + d) * DOUT + tx], w[(2 * DIN + d) * DOUT + tx + 32]);
#pragma unroll
        for (int t = 0; t < 16; t++) {
            const u64 x2 = xs2[(tok0 + t) * XS2_PAD + d];   // broadcast LDS.64
            fma2(acc[t][0], x2, wq);
            fma2(acc[t][1], x2, wk);
            fma2(acc[t][2], x2, wv);
        }
    }

    // store Q/K hi+lo (coalesced) and stage V in smem
#pragma unroll
    for (int t = 0; t < 16; t++) {
        const size_t row = (size_t)(b * SEQ + n0 + tok0 + t) * DOUT;
        float v0, v1;
        upk2(acc[t][0], v0, v1);
        v0 *= QSCALE; v1 *= QSCALE;
        __half h0 = __float2half_rn(v0), h1 = __float2half_rn(v1);
        g_qh[row + tx]      = h0; g_ql[row + tx]      = __float2half_rn(v0 - __half2float(h0));
        g_qh[row + tx + 32] = h1; g_ql[row + tx + 32] = __float2half_rn(v1 - __half2float(h1));
        upk2(acc[t][1], v0, v1);
        h0 = __float2half_rn(v0); h1 = __float2half_rn(v1);
        g_kh[row + tx]      = h0; g_kl[row + tx]      = __float2half_rn(v0 - __half2float(h0));
        g_kh[row + tx + 32] = h1; g_kl[row + tx + 32] = __float2half_rn(v1 - __half2float(h1));
        upk2(acc[t][2], v0, v1);
        vts[tx * VTS_PAD + tok0 + t]        = __float2half_rn(v0);
        vts[(tx + 32) * VTS_PAD + tok0 + t] = __float2half_rn(v1);
    }
    __syncthreads();

    // write V^T coalesced: row e -> 32 consecutive tokens per thread
    const int e = tid >> 2, seg = tid & 3;
    const u64* srcv = (const u64*)(vts + e * VTS_PAD + seg * 32);
    uint4* dstv = (uint4*)&g_vt[(((size_t)(b * DOUT + e)) << 12) + n0 + seg * 32];
    u64 r[8];
#pragma unroll
    for (int k = 0; k < 8; k++) r[k] = srcv[k];
#pragma unroll
    for (int k = 0; k < 4; k++)
        dstv[k] = make_uint4((uint32_t)r[2*k], (uint32_t)(r[2*k] >> 32),
                             (uint32_t)r[2*k+1], (uint32_t)(r[2*k+1] >> 32));
}

// ---------------------------------------------------------------------------
// Kernel 2: flash attention. QK restructured pass-major over jp-pairs to
// break HMMA accumulator RAW chains (spacing 1 -> 4).
// ---------------------------------------------------------------------------
__device__ __forceinline__ void load_kv_tiles(uint32_t smb, int stg,
                                              int b, int kt, int tid) {
    const __half* kh = g_kh + ((size_t)(b * SEQ + kt)) * DOUT;
    const __half* kl = g_kl + ((size_t)(b * SEQ + kt)) * DOUT;
    const __half* vt = g_vt + (((size_t)b * DOUT) << 12) + kt;
#pragma unroll
    for (int i = 0; i < 4; i++) {
        const int id = tid + i * 256;
        const int row = id >> 3, c = id & 7;
        cp16(smb + KH_B(stg) + row * 144 + c * 16, kh + row * DOUT + c * 8);
        cp16(smb + KL_B(stg) + row * 144 + c * 16, kl + row * DOUT + c * 8);
        const int d = id >> 4, cv = id & 15;
        cp16(smb + VT_B(stg) + d * 272 + cv * 16, vt + ((size_t)d << 12) + cv * 8);
    }
}

__global__ __launch_bounds__(256, 1)
void attn_kernel(float* __restrict__ out) {
    extern __shared__ __align__(128) char sm[];
    const uint32_t smb = smem_u32(sm);
    const int tid  = threadIdx.x;
    const int wid  = tid >> 5;
    const int lane = tid & 31;
    const int g    = lane >> 2;
    const int tq   = lane & 3;
    const int b    = blockIdx.y;
    const int q0   = blockIdx.x * BQ;
    const int r0   = wid * 16;

    const int lt = lane >> 3, lr = lane & 7;
    const uint32_t aoff  = (uint32_t)((r0 + ((lt & 1) << 3) + lr) * 144 + ((lt >> 1) << 4));
    const uint32_t kboff = (uint32_t)((((lane >> 4) << 3) + lr) * 144 + ((lt & 1) << 4));
    const uint32_t vboff = (uint32_t)((((lane >> 4) << 3) + lr) * 272 + ((lt & 1) << 4));

    // ---- prologue: Q + stages 0,1 ----
    {
        const __half* qh = g_qh + ((size_t)(b * SEQ + q0)) * DOUT;
        const __half* ql = g_ql + ((size_t)(b * SEQ + q0)) * DOUT;
#pragma unroll
        for (int i = 0; i < 4; i++) {
            const int id = tid + i * 256;
            const int row = id >> 3, c = id & 7;
            cp16(smb + QH_B + row * 144 + c * 16, qh + row * DOUT + c * 8);
            cp16(smb + QL_B + row * 144 + c * 16, ql + row * DOUT + c * 8);
        }
        load_kv_tiles(smb, 0, b, 0, tid);
        CP_COMMIT();
        load_kv_tiles(smb, 1, b, BK, tid);
        CP_COMMIT();
    }

    float o[8][4];
#pragma unroll
    for (int j = 0; j < 8; j++)
#pragma unroll
        for (int k = 0; k < 4; k++) o[j][k] = 0.f;
    float m0 = -3.0e38f, m1 = -3.0e38f, l0 = 0.f, l1 = 0.f;

    for (int t = 0; t < NTILES; t++) {
        CP_WAIT1();
        __syncthreads();
        if (t + 2 < NTILES)
            load_kv_tiles(smb, (t + 2) % 3, b, (t + 2) * BK, tid);
        CP_COMMIT();

        const int stg = t % 3;
        const uint32_t khb = smb + KH_B(stg) + kboff;
        const uint32_t klb = smb + KL_B(stg) + kboff;
        const uint32_t vtb = smb + VT_B(stg) + vboff;

        // ---- QK^T: pass-major over jp pairs; 4 live accumulators ----
        float s[16][4];
#pragma unroll
        for (int j = 0; j < 16; j++)
#pragma unroll
            for (int k = 0; k < 4; k++) s[j][k] = 0.f;

        uint32_t bh[2][8], bl[2][8];
        LDMX4(bh[0][0], bh[0][1], bh[0][2], bh[0][3], khb);
        LDMX4(bh[0][4], bh[0][5], bh[0][6], bh[0][7], khb + 2304);
        LDMX4(bl[0][0], bl[0][1], bl[0][2], bl[0][3], klb);
        LDMX4(bl[0][4], bl[0][5], bl[0][6], bl[0][7], klb + 2304);

#pragma unroll
        for (int ks = 0; ks < 4; ks++) {
            uint32_t ah0, ah1, ah2, ah3, al0, al1, al2, al3;
            LDMX4(ah0, ah1, ah2, ah3, smb + QH_B + aoff + ks * 32);
            LDMX4(al0, al1, al2, al3, smb + QL_B + aoff + ks * 32);
#pragma unroll
            for (int jpp = 0; jpp < 4; jpp++) {
                const int idx = ks * 4 + jpp;
                const int cur = idx & 1, nxt = cur ^ 1;
                if (idx < 15) {
                    const int nks = (jpp == 3) ? ks + 1 : ks;
                    const int njp = (jpp == 3) ? 0 : (jpp + 1) * 2;
                    const uint32_t nkh = khb + njp * 2304 + nks * 32;
                    const uint32_t nkl = klb + njp * 2304 + nks * 32;
                    LDMX4(bh[nxt][0], bh[nxt][1], bh[nxt][2], bh[nxt][3], nkh);
                    LDMX4(bh[nxt][4], bh[nxt][5], bh[nxt][6], bh[nxt][7], nkh + 2304);
                    LDMX4(bl[nxt][0], bl[nxt][1], bl[nxt][2], bl[nxt][3], nkl);
                    LDMX4(bl[nxt][4], bl[nxt][5], bl[nxt][6], bl[nxt][7], nkl + 2304);
                }
                float* sA0 = s[4 * jpp];     float* sA1 = s[4 * jpp + 1];
                float* sB0 = s[4 * jpp + 2]; float* sB1 = s[4 * jpp + 3];
                // pass hh
                MMA16816(sA0, ah0, ah1, ah2, ah3, bh[cur][0], bh[cur][1]);
                MMA16816(sA1, ah0, ah1, ah2, ah3, bh[cur][2], bh[cur][3]);
                MMA16816(sB0, ah0, ah1, ah2, ah3, bh[cur][4], bh[cur][5]);
                MMA16816(sB1, ah0, ah1, ah2, ah3, bh[cur][6], bh[cur][7]);
                // pass hl
                MMA16816(sA0, ah0, ah1, ah2, ah3, bl[cur][0], bl[cur][1]);
                MMA16816(sA1, ah0, ah1, ah2, ah3, bl[cur][2], bl[cur][3]);
                MMA16816(sB0, ah0, ah1, ah2, ah3, bl[cur][4], bl[cur][5]);
                MMA16816(sB1, ah0, ah1, ah2, ah3, bl[cur][6], bl[cur][7]);
                // pass lh
                MMA16816(sA0, al0, al1, al2, al3, bh[cur][0], bh[cur][1]);
                MMA16816(sA1, al0, al1, al2, al3, bh[cur][2], bh[cur][3]);
                MMA16816(sB0, al0, al1, al2, al3, bh[cur][4], bh[cur][5]);
                MMA16816(sB1, al0, al1, al2, al3, bh[cur][6], bh[cur][7]);
            }
        }

        // ---- online softmax in exp2 domain; P packed into PV A-fragments ----
        float mx0 = -3.0e38f, mx1 = -3.0e38f;
#pragma unroll
        for (int j = 0; j < 16; j++) {
            mx0 = fmaxf(mx0, fmaxf(s[j][0], s[j][1]));
            mx1 = fmaxf(mx1, fmaxf(s[j][2], s[j][3]));
        }
        mx0 = fmaxf(mx0, __shfl_xor_sync(0xffffffffu, mx0, 1));
        mx0 = fmaxf(mx0, __shfl_xor_sync(0xffffffffu, mx0, 2));
        mx1 = fmaxf(mx1, __shfl_xor_sync(0xffffffffu, mx1, 1));
        mx1 = fmaxf(mx1, __shfl_xor_sync(0xffffffffu, mx1, 2));
        const float mn0 = fmaxf(m0, mx0), mn1 = fmaxf(m1, mx1);
        const float c0 = ex2f(m0 - mn0), c1 = ex2f(m1 - mn1);

        uint32_t pa[8][4];
        float rs0 = 0.f, rs1 = 0.f;
#pragma unroll
        for (int j = 0; j < 16; j++) {
            const float e0 = ex2f(s[j][0] - mn0), e1 = ex2f(s[j][1] - mn0);
            const float e2 = ex2f(s[j][2] - mn1), e3 = ex2f(s[j][3] - mn1);
            rs0 += e0 + e1;  rs1 += e2 + e3;
            const __half2 h01 = __floats2half2_rn(e0, e1);
            const __half2 h23 = __floats2half2_rn(e2, e3);
            pa[j >> 1][(j & 1) * 2 + 0] = *(const uint32_t*)&h01;
            pa[j >> 1][(j & 1) * 2 + 1] = *(const uint32_t*)&h23;
        }
        rs0 += __shfl_xor_sync(0xffffffffu, rs0, 1);
        rs0 += __shfl_xor_sync(0xffffffffu, rs0, 2);
        rs1 += __shfl_xor_sync(0xffffffffu, rs1, 1);
        rs1 += __shfl_xor_sync(0xffffffffu, rs1, 2);
        l0 = l0 * c0 + rs0;  m0 = mn0;
        l1 = l1 * c1 + rs1;  m1 = mn1;

        // ---- PV: rescale then o += P @ V, double-buffered V fragments ----
#pragma unroll
        for (int j = 0; j < 8; j++) {
            o[j][0] *= c0; o[j][1] *= c0;
            o[j][2] *= c1; o[j][3] *= c1;
        }
        uint32_t vb[2][4];
        LDMX4(vb[0][0], vb[0][1], vb[0][2], vb[0][3], vtb);
#pragma unroll
        for (int ks = 0; ks < 8; ks++) {
#pragma unroll
            for (int jp = 0; jp < 4; jp++) {
                const int cur = (ks * 4 + jp) & 1, nxt = cur ^ 1;
                if (!(ks == 7 && jp == 3)) {
                    const uint32_t nv = (jp < 3) ? (vtb + ks * 32 + (jp + 1) * 4352)
                                                 : (vtb + (ks + 1) * 32);
                    LDMX4(vb[nxt][0], vb[nxt][1], vb[nxt][2], vb[nxt][3], nv);
                }
                MMA16816(o[2*jp],   pa[ks][0], pa[ks][1], pa[ks][2], pa[ks][3],
                         vb[cur][0], vb[cur][1]);
                MMA16816(o[2*jp+1], pa[ks][0], pa[ks][1], pa[ks][2], pa[ks][3],
                         vb[cur][2], vb[cur][3]);
            }
        }
    }

    // ---- epilogue ----
    const float rl0 = __frcp_rn(l0), rl1 = __frcp_rn(l1);
    float* O = out + ((size_t)(b * SEQ + q0 + r0 + g)) * DOUT;
#pragma unroll
    for (int j = 0; j < 8; j++) {
        const int col = j * 8 + 2 * tq;
        *(float2*)&O[col]            = make_float2(o[j][0] * rl0, o[j][1] * rl0);
        *(float2*)&O[8 * DOUT + col] = make_float2(o[j][2] * rl1, o[j][3] * rl1);
    }
}

// ---------------------------------------------------------------------------
extern "C" void kernel_launch(void* const* d_in, const int* in_sizes, int n_in,
                              void* d_out, int out_size) {
    const float* x = (const float*)d_in[0];   // [4,4096,128]
    const float* w = (const float*)d_in[1];   // [3,128,64]
    float* out = (float*)d_out;               // [4,4096,64]

    cudaFuncSetAttribute(attn_kernel,
                         cudaFuncAttributeMaxDynamicSharedMemorySize, SMEM_BYTES);
    cudaFuncSetAttribute(qkv_proj_kernel,
                         cudaFuncAttributeMaxDynamicSharedMemorySize, QKV_SMEM);

    qkv_proj_kernel<<<dim3(SEQ / 128, BATCH), 256, QKV_SMEM>>>(x, w);
    attn_kernel<<<dim3(SEQ / BQ, BATCH), 256, SMEM_BYTES>>>(out);
}